// round 2
// baseline (speedup 1.0000x reference)
#include <cuda_runtime.h>
#include <math.h>

#define L_DIM 16384
#define B_DIM 64
#define K_DIM 16
#define N_ROWS (B_DIM * K_DIM)   // 1024
#define CAP 4096                  // candidate buffer cap (expected ~30 used)

// Scratch (allocation-free rule: __device__ globals)
__device__ float g_nmask[B_DIM];
__device__ float g_row_loss[N_ROWS];

// ---------------------------------------------------------------------------
// Kernel A: per-batch mask sums  (64 blocks x 256 threads)
// ---------------------------------------------------------------------------
__global__ void mask_sum_kernel(const float* __restrict__ mask) {
    int b = blockIdx.x;
    const float4* m4 = (const float4*)(mask + (size_t)b * L_DIM);
    float s = 0.f;
    for (int i = threadIdx.x; i < L_DIM / 4; i += blockDim.x) {
        float4 v = m4[i];
        s += v.x + v.y + v.z + v.w;
    }
    #pragma unroll
    for (int o = 16; o; o >>= 1) s += __shfl_xor_sync(0xffffffffu, s, o);
    __shared__ float ws[8];
    int warp = threadIdx.x >> 5, lane = threadIdx.x & 31;
    if (lane == 0) ws[warp] = s;
    __syncthreads();
    if (threadIdx.x == 0) {
        float t = 0.f;
        #pragma unroll
        for (int w = 0; w < 8; w++) t += ws[w];
        g_nmask[b] = t;
    }
}

// ---------------------------------------------------------------------------
// Kernel B: per-(b,k) row — max, candidate gather, Michelot tau, loss terms.
// 1024 blocks x 512 threads.
// ---------------------------------------------------------------------------
__global__ void __launch_bounds__(512) row_kernel(
    const float* __restrict__ logits, const float* __restrict__ mask)
{
    __shared__ float sval[CAP];
    __shared__ int   sidx[CAP];
    __shared__ int   s_cnt;
    __shared__ float s_red[16];
    __shared__ float s_max;

    const int row = blockIdx.x;
    const int b = row >> 4;                 // row / K_DIM
    const float4* z4 = (const float4*)(logits + (size_t)row * L_DIM);
    const int tid = threadIdx.x;
    const int warp = tid >> 5, lane = tid & 31;

    // ---- pass 1: row max ----
    float m = -3.4e38f;
    #pragma unroll
    for (int it = 0; it < (L_DIM / 4) / 512; it++) {
        float4 v = z4[tid + it * 512];
        m = fmaxf(m, fmaxf(fmaxf(v.x, v.y), fmaxf(v.z, v.w)));
    }
    #pragma unroll
    for (int o = 16; o; o >>= 1) m = fmaxf(m, __shfl_xor_sync(0xffffffffu, m, o));
    if (lane == 0) s_red[warp] = m;
    if (tid == 0) s_cnt = 0;
    __syncthreads();
    if (tid == 0) {
        float t = s_red[0];
        #pragma unroll
        for (int w = 1; w < 16; w++) t = fmaxf(t, s_red[w]);
        s_max = t;
    }
    __syncthreads();
    const float thr = s_max - 1.0f;   // tau >= max-1, so support subset of {z > thr}

    // ---- pass 2: gather candidates (row is hot in L1/L2) ----
    #pragma unroll
    for (int it = 0; it < (L_DIM / 4) / 512; it++) {
        int i = tid + it * 512;
        float4 v = z4[i];
        if (v.x > thr) { int p = atomicAdd(&s_cnt, 1); if (p < CAP) { sval[p] = v.x; sidx[p] = 4 * i + 0; } }
        if (v.y > thr) { int p = atomicAdd(&s_cnt, 1); if (p < CAP) { sval[p] = v.y; sidx[p] = 4 * i + 1; } }
        if (v.z > thr) { int p = atomicAdd(&s_cnt, 1); if (p < CAP) { sval[p] = v.z; sidx[p] = 4 * i + 2; } }
        if (v.w > thr) { int p = atomicAdd(&s_cnt, 1); if (p < CAP) { sval[p] = v.w; sidx[p] = 4 * i + 3; } }
    }
    __syncthreads();
    const int cnt = min(s_cnt, CAP);

    // ---- warp 0: Michelot iteration for exact tau, then loss terms ----
    if (warp == 0) {
        float tau = -3.4e38f;
        for (int iter = 0; iter < 100; iter++) {
            float s = 0.f; int c = 0;
            for (int i = lane; i < cnt; i += 32) {
                float v = sval[i];
                if (v > tau) { s += v; c++; }
            }
            #pragma unroll
            for (int o = 16; o; o >>= 1) {
                s += __shfl_xor_sync(0xffffffffu, s, o);
                c += __shfl_xor_sync(0xffffffffu, c, o);
            }
            float nt = (s - 1.0f) / (float)c;   // c >= 1 always (max element stays active)
            if (nt == tau) break;
            tau = nt;
        }

        const float inv_n = 1.0f / fmaxf(g_nmask[b], 1e-12f);
        const float* mrow = mask + (size_t)b * L_DIM;
        float sp2 = 0.f, spm = 0.f;
        for (int i = lane; i < cnt; i += 32) {
            float p = sval[i] - tau;
            if (p > 0.f) {
                sp2 += p * p;
                spm += mrow[sidx[i]] * p;   // mask is 0/1; q = mask * inv_n
            }
        }
        #pragma unroll
        for (int o = 16; o; o >>= 1) {
            sp2 += __shfl_xor_sync(0xffffffffu, sp2, o);
            spm += __shfl_xor_sync(0xffffffffu, spm, o);
        }
        if (lane == 0) {
            // sum_L (p-q)^2 = sum p^2 - 2*inv_n*sum(p*mask) + 1/n_b
            g_row_loss[row] = 0.5f * (sp2 - 2.0f * inv_n * spm + inv_n);
        }
    }
}

// ---------------------------------------------------------------------------
// Kernel C: deterministic fixed-tree reduction of 1024 partials -> scalar
// ---------------------------------------------------------------------------
__global__ void final_reduce_kernel(float* __restrict__ out) {
    __shared__ float sh[512];
    int tid = threadIdx.x;
    sh[tid] = g_row_loss[tid] + g_row_loss[tid + 512];
    __syncthreads();
    #pragma unroll
    for (int o = 256; o > 0; o >>= 1) {
        if (tid < o) sh[tid] += sh[tid + o];
        __syncthreads();
    }
    if (tid == 0) out[0] = sh[0] * (1.0f / (float)N_ROWS);
}

// ---------------------------------------------------------------------------
extern "C" void kernel_launch(void* const* d_in, const int* in_sizes, int n_in,
                              void* d_out, int out_size) {
    const float* logits = (const float*)d_in[0];   // (64,16,16384) fp32
    const float* mask   = (const float*)d_in[1];   // (64,16384) fp32
    float* out = (float*)d_out;

    mask_sum_kernel<<<B_DIM, 256>>>(mask);
    row_kernel<<<N_ROWS, 512>>>(logits, mask);
    final_reduce_kernel<<<1, 512>>>(out);
}

// round 3
// speedup vs baseline: 1.4486x; 1.4486x over previous
#include <cuda_runtime.h>
#include <math.h>

#define L_DIM 16384
#define B_DIM 64
#define K_DIM 16
#define N_ROWS (B_DIM * K_DIM)     // 1024
#define MASK_BLOCKS B_DIM          // 64
#define TOTAL_BLOCKS (N_ROWS + MASK_BLOCKS)   // 1088
#define THREADS 256
#define ITERS (L_DIM / 4 / THREADS)           // 16
#define CAP 2048                   // candidate buffer (expected ~25 used)

// Scratch (allocation-free rule: __device__ globals)
__device__ float g_nmask[B_DIM];
__device__ float g_sp2[N_ROWS];
__device__ float g_spm[N_ROWS];
__device__ unsigned int g_done = 0;

__global__ void __launch_bounds__(THREADS) fused_kernel(
    const float* __restrict__ logits,
    const float* __restrict__ mask,
    float* __restrict__ out)
{
    __shared__ float sval[CAP];
    __shared__ int   sidx[CAP];
    __shared__ int   s_cnt;
    __shared__ float s_red[THREADS / 32];
    __shared__ float s_max;
    __shared__ float s_fin[THREADS];
    __shared__ unsigned int s_ticket;

    const int blk  = blockIdx.x;
    const int tid  = threadIdx.x;
    const int warp = tid >> 5, lane = tid & 31;

    if (blk >= N_ROWS) {
        // ----------------- mask-sum block (one per batch) -----------------
        const int b = blk - N_ROWS;
        const float4* m4 = (const float4*)(mask + (size_t)b * L_DIM);
        float s = 0.f;
        #pragma unroll
        for (int it = 0; it < ITERS; it++) {
            float4 v = m4[tid + it * THREADS];
            s += (v.x + v.y) + (v.z + v.w);
        }
        #pragma unroll
        for (int o = 16; o; o >>= 1) s += __shfl_xor_sync(0xffffffffu, s, o);
        if (lane == 0) s_red[warp] = s;
        __syncthreads();
        if (tid == 0) {
            float t = 0.f;
            #pragma unroll
            for (int w = 0; w < THREADS / 32; w++) t += s_red[w];
            g_nmask[b] = t;
        }
    } else {
        // ----------------------- row block (b,k) ---------------------------
        const int row = blk;
        const float4* z4 = (const float4*)(logits + (size_t)row * L_DIM);

        // ---- pass 1: row max (streams the row through DRAM into L2) ----
        float m = -3.4e38f;
        #pragma unroll
        for (int it = 0; it < ITERS; it++) {
            float4 v = z4[tid + it * THREADS];
            m = fmaxf(m, fmaxf(fmaxf(v.x, v.y), fmaxf(v.z, v.w)));
        }
        #pragma unroll
        for (int o = 16; o; o >>= 1) m = fmaxf(m, __shfl_xor_sync(0xffffffffu, m, o));
        if (lane == 0) s_red[warp] = m;
        if (tid == 0) s_cnt = 0;
        __syncthreads();
        if (tid == 0) {
            float t = s_red[0];
            #pragma unroll
            for (int w = 1; w < THREADS / 32; w++) t = fmaxf(t, s_red[w]);
            s_max = t;
        }
        __syncthreads();
        // tau >= max-1 (support always contains argmax), so support ⊆ {z > max-1}
        const float thr = s_max - 1.0f;

        // ---- pass 2: gather candidates (row is hot in L2) ----
        #pragma unroll
        for (int it = 0; it < ITERS; it++) {
            int i = tid + it * THREADS;
            float4 v = z4[i];
            if (v.x > thr) { int p = atomicAdd(&s_cnt, 1); if (p < CAP) { sval[p] = v.x; sidx[p] = 4 * i + 0; } }
            if (v.y > thr) { int p = atomicAdd(&s_cnt, 1); if (p < CAP) { sval[p] = v.y; sidx[p] = 4 * i + 1; } }
            if (v.z > thr) { int p = atomicAdd(&s_cnt, 1); if (p < CAP) { sval[p] = v.z; sidx[p] = 4 * i + 2; } }
            if (v.w > thr) { int p = atomicAdd(&s_cnt, 1); if (p < CAP) { sval[p] = v.w; sidx[p] = 4 * i + 3; } }
        }
        __syncthreads();
        const int cnt = min(s_cnt, CAP);

        // ---- warp 0: Michelot iteration for exact tau, then loss terms ----
        if (warp == 0) {
            float tau = -3.4e38f;
            for (int iter = 0; iter < 100; iter++) {
                float s = 0.f; int c = 0;
                for (int i = lane; i < cnt; i += 32) {
                    float v = sval[i];
                    if (v > tau) { s += v; c++; }
                }
                #pragma unroll
                for (int o = 16; o; o >>= 1) {
                    s += __shfl_xor_sync(0xffffffffu, s, o);
                    c += __shfl_xor_sync(0xffffffffu, c, o);
                }
                float nt = (s - 1.0f) / (float)c;   // c >= 1 always
                if (nt == tau) break;
                tau = nt;
            }

            const int b = row >> 4;
            const float* mrow = mask + (size_t)b * L_DIM;
            float sp2 = 0.f, spm = 0.f;
            for (int i = lane; i < cnt; i += 32) {
                float p = sval[i] - tau;
                if (p > 0.f) {
                    sp2 += p * p;
                    spm += mrow[sidx[i]] * p;   // mask is 0/1; q = mask * inv_n applied later
                }
            }
            #pragma unroll
            for (int o = 16; o; o >>= 1) {
                sp2 += __shfl_xor_sync(0xffffffffu, sp2, o);
                spm += __shfl_xor_sync(0xffffffffu, spm, o);
            }
            if (lane == 0) {
                g_sp2[row] = sp2;
                g_spm[row] = spm;
            }
        }
    }

    // ------------- last-block-done final reduction (deterministic) ---------
    __syncthreads();           // all block work (incl. warp-0 stores) issued
    __threadfence();           // make g_* writes visible device-wide
    if (tid == 0) s_ticket = atomicAdd(&g_done, 1u);
    __syncthreads();
    if (s_ticket == TOTAL_BLOCKS - 1) {
        // Fixed read order + fixed tree => bitwise deterministic result.
        float acc = 0.f;
        #pragma unroll
        for (int j = 0; j < N_ROWS / THREADS; j++) {
            int r = tid + j * THREADS;
            int b = r >> 4;
            float inv_n = 1.0f / fmaxf(g_nmask[b], 1e-12f);
            acc += 0.5f * g_sp2[r] - inv_n * g_spm[r] + 0.5f * inv_n;
        }
        s_fin[tid] = acc;
        __syncthreads();
        #pragma unroll
        for (int o = THREADS / 2; o > 0; o >>= 1) {
            if (tid < o) s_fin[tid] += s_fin[tid + o];
            __syncthreads();
        }
        if (tid == 0) {
            out[0] = s_fin[0] * (1.0f / (float)N_ROWS);
            g_done = 0;        // reset for next graph replay
        }
    }
}

// ---------------------------------------------------------------------------
extern "C" void kernel_launch(void* const* d_in, const int* in_sizes, int n_in,
                              void* d_out, int out_size) {
    const float* logits = (const float*)d_in[0];   // (64,16,16384) fp32
    const float* mask   = (const float*)d_in[1];   // (64,16384) fp32
    float* out = (float*)d_out;

    fused_kernel<<<TOTAL_BLOCKS, THREADS>>>(logits, mask, out);
}